// round 8
// baseline (speedup 1.0000x reference)
#include <cuda_runtime.h>
#include <math.h>

// ---------------- problem constants ----------------
#define DXV   10000
#define DRV   5000
#define NANC  2000
#define NNODE 18000     // DXV + SPLIT*NANC
#define Dm    128
#define ECNT  200000
#define NBV   640       // B*V
#define NCODE 80
#define NDX   40
#define LBL   2000
#define MAXDEG 192

#define B_H    563      // ceil(18000/32)
#define B_DR   157      // ceil(5000/32)
#define B_SDX  313      // ceil(10000/32)

typedef unsigned long long ULL;

// ---------------- scratch ----------------
__device__ float g_classEmb[DXV * Dm];
__device__ float g_h[NNODE * Dm];
__device__ float g_el[NNODE];
__device__ float g_er[NNODE];
__device__ int   g_count[DXV];      // zero at load; re-zeroed by k_scatter each call
__device__ int   g_rowoff[DXV + 1];
__device__ int   g_rank[ECNT];
__device__ int   g_eid[ECNT];
__device__ float g_dxALLonto[DXV * Dm];
__device__ float g_SdxA[DXV * Dm];  // static half: dxEmb @ attnW[0:128]
__device__ float g_Sdx[DXV * Dm];
__device__ float g_Sdrug[DRV * Dm];
__device__ float g_visit[NBV * 2 * Dm];

// ---------------- helpers ----------------
__device__ __forceinline__ float warpSum(float x) {
    #pragma unroll
    for (int o = 16; o; o >>= 1) x += __shfl_xor_sync(0xffffffffu, x, o);
    return x;
}
__device__ __forceinline__ float warpMax(float x) {
    #pragma unroll
    for (int o = 16; o; o >>= 1) x = fmaxf(x, __shfl_xor_sync(0xffffffffu, x, o));
    return x;
}
__device__ __forceinline__ float blockSum128(float x, float* sh) {
    int w = threadIdx.x >> 5, l = threadIdx.x & 31;
    x = warpSum(x);
    if (l == 0) sh[w] = x;
    __syncthreads();
    float r = sh[0] + sh[1] + sh[2] + sh[3];
    __syncthreads();
    return r;
}
__device__ __forceinline__ float blockMax128(float x, float* sh) {
    int w = threadIdx.x >> 5, l = threadIdx.x & 31;
    x = warpMax(x);
    if (l == 0) sh[w] = x;
    __syncthreads();
    float r = fmaxf(fmaxf(sh[0], sh[1]), fmaxf(sh[2], sh[3]));
    __syncthreads();
    return r;
}
__device__ __forceinline__ float fast_tanh(float x) {
    float y;
    asm("tanh.approx.f32 %0, %1;" : "=f"(y) : "f"(x));
    return y;
}
// packed fp32x2 FMA (FFMA2)
__device__ __forceinline__ ULL pk2(float lo, float hi) {
    ULL r; asm("mov.b64 %0, {%1, %2};" : "=l"(r) : "f"(lo), "f"(hi)); return r;
}
__device__ __forceinline__ void ffma2(ULL& d, ULL a, ULL b) {
    asm("fma.rn.f32x2 %0, %1, %2, %0;" : "+l"(d) : "l"(a), "l"(b));
}
__device__ __forceinline__ float fold2(ULL a) {
    float lo, hi; asm("mov.b64 {%0, %1}, %2;" : "=f"(lo), "=f"(hi) : "l"(a));
    return lo + hi;
}

// 32-row x 128-col GEMM tile core (k-paired FFMA2), K = 4*K4.
template<int K4, class F>
__device__ __forceinline__ void gemm32(const ulonglong2* __restrict__ sn,
                                       const float* __restrict__ wcol, int wstride,
                                       F emit) {
    ULL acc[32];
    #pragma unroll
    for (int r = 0; r < 32; r++) acc[r] = 0ull;
    #pragma unroll 2
    for (int k4 = 0; k4 < K4; k4++) {
        const float* wp = wcol + (k4 * 4) * wstride;
        ULL w01 = pk2(__ldg(wp), __ldg(wp + wstride));
        ULL w23 = pk2(__ldg(wp + 2 * wstride), __ldg(wp + 3 * wstride));
        #pragma unroll
        for (int r = 0; r < 32; r++) {
            ulonglong2 x = sn[r * K4 + k4];
            ffma2(acc[r], x.x, w01);
            ffma2(acc[r], x.y, w23);
        }
    }
    #pragma unroll
    for (int r = 0; r < 32; r++) emit(r, fold2(acc[r]));
}

// =====================================================================
// L1: count incoming edges per dx dst + record per-edge rank
// =====================================================================
__global__ void k_count(const int* __restrict__ dst) {
    int i = blockIdx.x * blockDim.x + threadIdx.x;
    if (i < ECNT) {
        int d = dst[i];
        if (d < DXV) g_rank[i] = atomicAdd(&g_count[d], 1);
    }
}

// =====================================================================
// L2: single-block two-level exclusive scan (1024 thr, 10 elems each)
// =====================================================================
__global__ void k_scan() {
    __shared__ int wsum[32];
    const int tid = threadIdx.x, l = tid & 31, w = tid >> 5;
    int pre[10];
    int s = 0;
    #pragma unroll
    for (int k = 0; k < 10; k++) {
        int idx = tid * 10 + k;
        int v = (idx < DXV) ? g_count[idx] : 0;
        pre[k] = s; s += v;
    }
    int x = s;
    #pragma unroll
    for (int o = 1; o < 32; o <<= 1) {
        int y = __shfl_up_sync(0xffffffffu, x, o);
        if (l >= o) x += y;
    }
    if (l == 31) wsum[w] = x;
    __syncthreads();
    if (w == 0) {
        int ws = wsum[l];
        #pragma unroll
        for (int o = 1; o < 32; o <<= 1) {
            int y = __shfl_up_sync(0xffffffffu, ws, o);
            if (l >= o) ws += y;
        }
        wsum[l] = ws;
    }
    __syncthreads();
    int texcl = ((w > 0) ? wsum[w - 1] : 0) + x - s;
    #pragma unroll
    for (int k = 0; k < 10; k++) {
        int idx = tid * 10 + k;
        if (idx < DXV) g_rowoff[idx] = texcl + pre[k];
    }
    if (tid == 0) g_rowoff[DXV] = wsum[31];
}

// =====================================================================
// L3: atomic-free scatter + re-zero counts for next call
// =====================================================================
__global__ void k_scatter(const int* __restrict__ dst) {
    int i = blockIdx.x * blockDim.x + threadIdx.x;
    if (i < ECNT) {
        int d = dst[i];
        if (d < DXV) g_eid[g_rowoff[d] + g_rank[i]] = i;
    }
    if (i < DXV) g_count[i] = 0;
}

// =====================================================================
// L4 FRONT (profiled slot): h+el/er | drug score | Sdx static
// =====================================================================
__global__ void k_front(const float* __restrict__ dxEmb, const float* __restrict__ extra,
                        const float* __restrict__ W, const float* __restrict__ al,
                        const float* __restrict__ ar,
                        const float* __restrict__ drEmb, const float* __restrict__ drEmb2,
                        const float* __restrict__ attnW) {
    __shared__ __align__(16) float4 sn4[32 * 64];   // 32KB
    __shared__ float pel[128];
    __shared__ float per[128];
    const int bid = blockIdx.x, tid = threadIdx.x;
    const int l = tid & 31, w = tid >> 5;

    if (bid < B_H) {
        // ---- h = nodes @ gat_W (32 rows) + fused el/er ----
        const int r0 = bid * 32;
        for (int i = tid; i < 32 * 32; i += 128) {
            int rr = i >> 5, c4 = i & 31;
            int row = r0 + rr;
            float4 v = make_float4(0.f, 0.f, 0.f, 0.f);
            if (row < NNODE)
                v = (row < DXV) ? ((const float4*)dxEmb)[row * 32 + c4]
                                : ((const float4*)extra)[(row - DXV) * 32 + c4];
            sn4[i] = v;
        }
        __syncthreads();
        float a_t = __ldg(al + tid), b_t = __ldg(ar + tid);
        gemm32<32>((const ulonglong2*)sn4, W + tid, Dm,
            [&](int rr, float hv) {
                int row = r0 + rr;
                if (row < NNODE) g_h[(long)row * Dm + tid] = hv;
                float ea = warpSum(hv * a_t);
                float eb = warpSum(hv * b_t);
                if (l == 0) { pel[rr * 4 + w] = ea; per[rr * 4 + w] = eb; }
            });
        __syncthreads();
        if (tid < 32) {
            int row = r0 + tid;
            if (row < NNODE)
                g_el[row] = pel[tid * 4] + pel[tid * 4 + 1] + pel[tid * 4 + 2] + pel[tid * 4 + 3];
        } else if (tid < 64) {
            int rr = tid - 32, row = r0 + rr;
            if (row < NNODE)
                g_er[row] = per[rr * 4] + per[rr * 4 + 1] + per[rr * 4 + 2] + per[rr * 4 + 3];
        }
    } else if (bid < B_H + B_DR) {
        // ---- drug score table (K=256): drEmb@W[0:128] + drEmb2@W[128:256] ----
        const int r0 = (bid - B_H) * 32;
        for (int i = tid; i < 32 * 64; i += 128) {
            int rr = i >> 6, c4 = i & 63;
            int row = r0 + rr;
            float4 v = make_float4(0.f, 0.f, 0.f, 0.f);
            if (row < DRV)
                v = (c4 < 32) ? ((const float4*)drEmb)[row * 32 + c4]
                              : ((const float4*)drEmb2)[row * 32 + (c4 - 32)];
            sn4[i] = v;
        }
        __syncthreads();
        gemm32<64>((const ulonglong2*)sn4, attnW + tid, Dm,
            [&](int rr, float v) {
                int row = r0 + rr;
                if (row < DRV) g_Sdrug[(long)row * Dm + tid] = v;
            });
    } else {
        // ---- Sdx static half (K=128): dxEmb @ attnW[0:128] ----
        const int r0 = (bid - B_H - B_DR) * 32;
        for (int i = tid; i < 32 * 32; i += 128) {
            int rr = i >> 5, c4 = i & 31;
            int row = r0 + rr;
            sn4[i] = (row < DXV) ? ((const float4*)dxEmb)[row * 32 + c4]
                                 : make_float4(0.f, 0.f, 0.f, 0.f);
        }
        __syncthreads();
        gemm32<32>((const ulonglong2*)sn4, attnW + tid, Dm,
            [&](int rr, float v) {
                int row = r0 + rr;
                if (row < DXV) g_SdxA[(long)row * Dm + tid] = v;
            });
    }
}

// =====================================================================
// L5: classEmb = L2norm(sparse(dx2anc row) @ S)   (one block per row)
// =====================================================================
__global__ void k_classEmb(const float* __restrict__ A, const float* __restrict__ S) {
    const int row = blockIdx.x, tid = threadIdx.x;
    const int l = tid & 31, w = tid >> 5;
    __shared__ float sval[512];
    __shared__ short sidx[512];
    __shared__ int   scnt[4];
    __shared__ float sred[4];
    const float4* r4 = (const float4*)(A + (long)row * NANC);

    float4 va[4];
    #pragma unroll
    for (int q = 0; q < 4; q++) {
        int f4 = tid * 4 + q;
        va[q] = (f4 < NANC / 4) ? __ldg(r4 + f4) : make_float4(0.f, 0.f, 0.f, 0.f);
    }
    const float* vf = (const float*)va;
    int base = 0;
    #pragma unroll
    for (int t = 0; t < 16; t++) {
        float v = vf[t];
        int a = tid * 16 + t;
        bool nz = (v != 0.f);
        unsigned mask = __ballot_sync(0xffffffffu, nz);
        if (nz) {
            int p = base + __popc(mask & ((1u << l) - 1u));
            if (p < 128) { sval[w * 128 + p] = v; sidx[w * 128 + p] = (short)a; }
        }
        base += __popc(mask);
    }
    if (l == 0) scnt[w] = (base < 128) ? base : 128;
    __syncthreads();
    float acc = 0.f;
    for (int ww = 0; ww < 4; ww++) {
        int c = scnt[ww];
        #pragma unroll 2
        for (int j = 0; j < c; j++)
            acc += sval[ww * 128 + j] * __ldg(S + (int)sidx[ww * 128 + j] * Dm + tid);
    }
    float ss = blockSum128(acc * acc, sred);
    g_classEmb[(long)row * Dm + tid] = acc / (sqrtf(ss) + 1e-12f);
}

// =====================================================================
// L6: GAT softmax-aggregate per dst + fuse classEmb (warp-split j)
// =====================================================================
__global__ void k_agg(const int* __restrict__ esrc) {
    const int d = blockIdx.x, tid = threadIdx.x;
    const int lane = tid & 31, w = tid >> 5;
    __shared__ int   sid[MAXDEG];
    __shared__ int   ssrc[MAXDEG];
    __shared__ float sw[MAXDEG];
    __shared__ float shred[4];
    __shared__ float spart[4][128];

    int base = g_rowoff[d];
    int n = g_rowoff[d + 1] - base;
    if (n > MAXDEG) n = MAXDEG;

    for (int j = tid; j < n; j += 128) sid[j] = g_eid[base + j];
    __syncthreads();
    // deterministic ascending edge-id order via rank sort (ids unique, n small)
    for (int j = tid; j < n; j += 128) {
        int id = sid[j];
        int rk = 0;
        for (int k = 0; k < n; k++) rk += (sid[k] < id);
        ssrc[rk] = id;
    }
    __syncthreads();
    float er_d = g_er[d];
    for (int j = tid; j < n; j += 128) {
        int s = esrc[ssrc[j]];
        float x = g_el[s] + er_d;
        sw[j] = (x >= 0.f) ? x : 0.2f * x;
        ssrc[j] = s;
    }
    __syncthreads();
    float m = -1e30f;
    for (int j = tid; j < n; j += 128) m = fmaxf(m, sw[j]);
    m = blockMax128(m, shred);
    float ps = 0.f;
    for (int j = tid; j < n; j += 128) {
        float ww = __expf(sw[j] - m);
        sw[j] = ww;
        ps += ww;
    }
    float inv = 1.f / (blockSum128(ps, shred) + 1e-9f);

    // warp-split aggregate: warp w takes j ≡ w (mod 4); each thread holds
    // 4 columns (lane+0/32/64/96). Fixed assignment + fixed reduce order
    // => deterministic.
    float a0 = 0.f, a1 = 0.f, a2 = 0.f, a3 = 0.f;
    #pragma unroll 2
    for (int j = w; j < n; j += 4) {
        float wt = sw[j];
        const float* hp = g_h + (long)ssrc[j] * Dm + lane;
        a0 += wt * hp[0];
        a1 += wt * hp[32];
        a2 += wt * hp[64];
        a3 += wt * hp[96];
    }
    spart[w][lane]      = a0;
    spart[w][lane + 32] = a1;
    spart[w][lane + 64] = a2;
    spart[w][lane + 96] = a3;
    __syncthreads();
    float acc = spart[0][tid] + spart[1][tid] + spart[2][tid] + spart[3][tid];
    g_dxALLonto[(long)d * Dm + tid] = acc * inv + g_classEmb[(long)d * Dm + tid];
}

// =====================================================================
// L7: Sdx = SdxA + dxALLonto @ attnW[128:256]   (K=128 only)
// =====================================================================
__global__ void k_scoreDx2(const float* __restrict__ attnW) {
    __shared__ __align__(16) float4 sn4[32 * 32];   // 16KB
    const int tid = threadIdx.x;
    const int r0 = blockIdx.x * 32;
    for (int i = tid; i < 32 * 32; i += 128) {
        int rr = i >> 5, c4 = i & 31;
        int row = r0 + rr;
        sn4[i] = (row < DXV) ? ((const float4*)g_dxALLonto)[row * 32 + c4]
                             : make_float4(0.f, 0.f, 0.f, 0.f);
    }
    __syncthreads();
    gemm32<32>((const ulonglong2*)sn4, attnW + Dm * Dm + tid, Dm,
        [&](int rr, float v) {
            int row = r0 + rr;
            if (row < DXV)
                g_Sdx[(long)row * Dm + tid] = g_SdxA[(long)row * Dm + tid] + v;
        });
}

// =====================================================================
// L8: per-visit attention
// =====================================================================
__global__ void k_visit(const int* __restrict__ dxseqs, const int* __restrict__ drugseqs,
                        const float* __restrict__ dxEmb, const float* __restrict__ drEmb,
                        const float* __restrict__ drEmb2, const float* __restrict__ attnW,
                        const float* __restrict__ attnB, const float* __restrict__ combW,
                        const float* __restrict__ combB) {
    const int bv = blockIdx.x, tid = threadIdx.x;
    __shared__ int   sh_idx[NCODE];
    __shared__ __align__(16) float s_u[256];
    __shared__ float s_up[Dm];
    __shared__ float s_sc[NCODE];
    __shared__ float s_alpha[NCODE];
    __shared__ float shred[4];

    if (tid < NDX)        sh_idx[tid] = dxseqs[bv * NDX + tid];
    else if (tid < NCODE) sh_idx[tid] = drugseqs[bv * NDX + (tid - NDX)];
    __syncthreads();

    float u0 = 0.f, u1 = 0.f;
    #pragma unroll 4
    for (int k = 0; k < NCODE; k++) {
        int id = sh_idx[k];
        const float *p0, *p1;
        if (k < NDX) { p0 = dxEmb + (long)id * Dm; p1 = g_dxALLonto + (long)id * Dm; }
        else         { p0 = drEmb + (long)id * Dm; p1 = drEmb2 + (long)id * Dm; }
        u0 += p0[tid];
        u1 += p1[tid];
    }
    s_u[tid] = u0 * (1.f / NCODE);
    s_u[Dm + tid] = u1 * (1.f / NCODE);
    __syncthreads();

    {   // u_part = u @ attnW[256:512] + attn_b   (k-paired FFMA2)
        const ULL* su64 = (const ULL*)s_u;
        ULL up2 = 0ull;
        #pragma unroll 4
        for (int k2 = 0; k2 < 128; k2++) {
            ULL wv = pk2(__ldg(attnW + (256 + 2 * k2) * Dm + tid),
                         __ldg(attnW + (257 + 2 * k2) * Dm + tid));
            ffma2(up2, su64[k2], wv);
        }
        s_up[tid] = __ldg(attnB + tid) + fold2(up2);
    }
    __syncthreads();

    const int w = tid >> 5, lane = tid & 31;
    const float cb = __ldg(combB);
    for (int k = w; k < NCODE; k += 4) {
        int id = sh_idx[k];
        const float* base = (k < NDX) ? (g_Sdx + (long)id * Dm) : (g_Sdrug + (long)id * Dm);
        float t = 0.f;
        #pragma unroll
        for (int q = 0; q < 4; q++) {
            int d = lane + 32 * q;
            t += fast_tanh(base[d] + s_up[d]) * __ldg(combW + d);
        }
        t = warpSum(t);
        if (lane == 0) s_sc[k] = t + cb;
    }
    __syncthreads();

    float sv = (tid < NCODE) ? s_sc[tid] : -1e30f;
    float m = blockMax128(sv, shred);
    float e = (tid < NCODE) ? __expf(sv - m) : 0.f;
    float Z = blockSum128(e, shred);
    if (tid < NCODE) s_alpha[tid] = e / Z;
    __syncthreads();

    float v0 = 0.f, v1 = 0.f;
    #pragma unroll 4
    for (int k = 0; k < NCODE; k++) {
        float a = s_alpha[k];
        int id = sh_idx[k];
        const float *p0, *p1;
        if (k < NDX) { p0 = dxEmb + (long)id * Dm; p1 = g_dxALLonto + (long)id * Dm; }
        else         { p0 = drEmb + (long)id * Dm; p1 = drEmb2 + (long)id * Dm; }
        v0 += a * p0[tid];
        v1 += a * p1[tid];
    }
    g_visit[bv * 256 + tid] = v0;
    g_visit[bv * 256 + Dm + tid] = v1;
}

// =====================================================================
// L9: out = sigmoid(visit @ dp_W + dp_b)   (32-row tiles)
// =====================================================================
__global__ void k_dp(const float* __restrict__ dpW, const float* __restrict__ dpB,
                     float* __restrict__ out) {
    __shared__ __align__(16) float4 sv4[32 * 64];
    const int tid = threadIdx.x;
    const int l = blockIdx.x * 128 + tid;
    const int r0 = blockIdx.y * 32;
    for (int i = tid; i < 32 * 64; i += 128)
        sv4[i] = ((const float4*)g_visit)[r0 * 64 + i];
    __syncthreads();
    if (l >= LBL) return;
    float b = __ldg(dpB + l);
    gemm32<64>((const ulonglong2*)sv4, dpW + l, LBL,
        [&](int rr, float v) {
            float x = v + b;
            out[(long)(r0 + rr) * LBL + l] = 1.f / (1.f + __expf(-x));
        });
}

// ---------------- launcher ----------------
extern "C" void kernel_launch(void* const* d_in, const int* in_sizes, int n_in,
                              void* d_out, int out_size) {
    const int*   dxseqs  = (const int*)d_in[0];
    const int*   drugseqs= (const int*)d_in[1];
    const int*   esrc    = (const int*)d_in[2];
    const int*   edst    = (const int*)d_in[3];
    const float* dx2anc  = (const float*)d_in[4];
    const float* dxEmb   = (const float*)d_in[5];
    const float* drEmb   = (const float*)d_in[6];
    const float* drEmb2  = (const float*)d_in[7];
    const float* extra   = (const float*)d_in[8];
    const float* S       = (const float*)d_in[9];
    const float* gatW    = (const float*)d_in[10];
    const float* gal     = (const float*)d_in[11];
    const float* gar     = (const float*)d_in[12];
    const float* attnW   = (const float*)d_in[13];
    const float* attnB   = (const float*)d_in[14];
    const float* combW   = (const float*)d_in[15];
    const float* combB   = (const float*)d_in[16];
    const float* dpW     = (const float*)d_in[17];
    const float* dpB     = (const float*)d_in[18];
    float*       out     = (float*)d_out;

    // CSR chain first (independent of embeddings); k_front lands in the
    // profiler's captured slot (4th launch).
    k_count<<<(ECNT + 255) / 256, 256>>>(edst);
    k_scan<<<1, 1024>>>();
    k_scatter<<<(ECNT + 255) / 256, 256>>>(edst);
    k_front<<<B_H + B_DR + B_SDX, 128>>>(dxEmb, extra, gatW, gal, gar,
                                         drEmb, drEmb2, attnW);
    k_classEmb<<<DXV, 128>>>(dx2anc, S);
    k_agg<<<DXV, 128>>>(esrc);
    k_scoreDx2<<<B_SDX, 128>>>(attnW);
    k_visit<<<NBV, 128>>>(dxseqs, drugseqs, dxEmb, drEmb, drEmb2,
                          attnW, attnB, combW, combB);
    k_dp<<<dim3((LBL + 127) / 128, NBV / 32), 128>>>(dpW, dpB, out);
}

// round 9
// speedup vs baseline: 1.0605x; 1.0605x over previous
#include <cuda_runtime.h>
#include <math.h>

// ---------------- problem constants ----------------
#define DXV   10000
#define DRV   5000
#define NANC  2000
#define NNODE 18000     // DXV + SPLIT*NANC
#define Dm    128
#define ECNT  200000
#define NBV   640       // B*V
#define NCODE 80
#define NDX   40
#define LBL   2000
#define MAXDEG 192

#define B_H    563      // ceil(18000/32)
#define B_DR   157      // ceil(5000/32)
#define B_SDX  313      // ceil(10000/32)
#define B_CNT  391      // ceil(200000/512)

typedef unsigned long long ULL;

// ---------------- scratch ----------------
__device__ float g_classEmb[DXV * Dm];
__device__ float g_h[NNODE * Dm];
__device__ float g_el[NNODE];
__device__ float g_er[NNODE];
__device__ int   g_count[DXV];      // zero at load; re-zeroed by k_scatter each call
__device__ int   g_rowoff[DXV + 1];
__device__ int   g_rank[ECNT];
__device__ int   g_eid[ECNT];
__device__ float g_dxALLonto[DXV * Dm];
__device__ float g_SdxA[DXV * Dm];  // static half: dxEmb @ attnW[0:128]
__device__ float g_Sdx[DXV * Dm];
__device__ float g_Sdrug[DRV * Dm];
__device__ float g_visit[NBV * 2 * Dm];

// ---------------- helpers ----------------
__device__ __forceinline__ float warpSum(float x) {
    #pragma unroll
    for (int o = 16; o; o >>= 1) x += __shfl_xor_sync(0xffffffffu, x, o);
    return x;
}
__device__ __forceinline__ float warpMax(float x) {
    #pragma unroll
    for (int o = 16; o; o >>= 1) x = fmaxf(x, __shfl_xor_sync(0xffffffffu, x, o));
    return x;
}
__device__ __forceinline__ float blockSum128(float x, float* sh) {
    int w = threadIdx.x >> 5, l = threadIdx.x & 31;
    x = warpSum(x);
    if (l == 0) sh[w] = x;
    __syncthreads();
    float r = sh[0] + sh[1] + sh[2] + sh[3];
    __syncthreads();
    return r;
}
__device__ __forceinline__ float blockMax128(float x, float* sh) {
    int w = threadIdx.x >> 5, l = threadIdx.x & 31;
    x = warpMax(x);
    if (l == 0) sh[w] = x;
    __syncthreads();
    float r = fmaxf(fmaxf(sh[0], sh[1]), fmaxf(sh[2], sh[3]));
    __syncthreads();
    return r;
}
__device__ __forceinline__ float fast_tanh(float x) {
    float y;
    asm("tanh.approx.f32 %0, %1;" : "=f"(y) : "f"(x));
    return y;
}
// packed fp32x2 FMA (FFMA2)
__device__ __forceinline__ ULL pk2(float lo, float hi) {
    ULL r; asm("mov.b64 %0, {%1, %2};" : "=l"(r) : "f"(lo), "f"(hi)); return r;
}
__device__ __forceinline__ void ffma2(ULL& d, ULL a, ULL b) {
    asm("fma.rn.f32x2 %0, %1, %2, %0;" : "+l"(d) : "l"(a), "l"(b));
}
__device__ __forceinline__ float fold2(ULL a) {
    float lo, hi; asm("mov.b64 {%0, %1}, %2;" : "=f"(lo), "=f"(hi) : "l"(a));
    return lo + hi;
}

// 16-row x 2-col GEMM tile core (k-paired FFMA2), K = 4*K4.
// sn: this row-group's 16 rows (row-major ulonglong2, K4 per row).
// wbase = W + c0 (c0 even); weight rows loaded as float2 covering cols c0,c0+1.
// emit(r, v_c0, v_c1).
template<int K4, class F>
__device__ __forceinline__ void gemm16x2(const ulonglong2* __restrict__ sn,
                                         const float* __restrict__ wbase, int wstride,
                                         F emit) {
    ULL acc0[16], acc1[16];
    #pragma unroll
    for (int r = 0; r < 16; r++) { acc0[r] = 0ull; acc1[r] = 0ull; }
    #pragma unroll 2
    for (int k4 = 0; k4 < K4; k4++) {
        const float* wp = wbase + (k4 * 4) * wstride;
        float2 v0 = __ldg((const float2*)(wp));
        float2 v1 = __ldg((const float2*)(wp + wstride));
        float2 v2 = __ldg((const float2*)(wp + 2 * wstride));
        float2 v3 = __ldg((const float2*)(wp + 3 * wstride));
        ULL w01a = pk2(v0.x, v1.x), w01b = pk2(v0.y, v1.y);
        ULL w23a = pk2(v2.x, v3.x), w23b = pk2(v2.y, v3.y);
        #pragma unroll
        for (int r = 0; r < 16; r++) {
            ulonglong2 x = sn[r * K4 + k4];
            ffma2(acc0[r], x.x, w01a);
            ffma2(acc0[r], x.y, w23a);
            ffma2(acc1[r], x.x, w01b);
            ffma2(acc1[r], x.y, w23b);
        }
    }
    #pragma unroll
    for (int r = 0; r < 16; r++) emit(r, fold2(acc0[r]), fold2(acc1[r]));
}

// =====================================================================
// L1 FRONT: h+el/er | drug score | Sdx static | edge count
// =====================================================================
__global__ void k_front(const float* __restrict__ dxEmb, const float* __restrict__ extra,
                        const float* __restrict__ W, const float* __restrict__ al,
                        const float* __restrict__ ar,
                        const float* __restrict__ drEmb, const float* __restrict__ drEmb2,
                        const float* __restrict__ attnW,
                        const int* __restrict__ edst) {
    __shared__ __align__(16) float4 sn4[32 * 64];   // 32KB
    __shared__ float pel[32][2];
    __shared__ float per[32][2];
    const int bid = blockIdx.x, tid = threadIdx.x;
    const int lane = tid & 31, wp2 = (tid >> 5) & 1;  // warp-in-rowgroup
    const int t64 = tid & 63, rowgrp = tid >> 6;
    const int c0 = 2 * t64;

    if (bid < B_H) {
        // ---- h = nodes @ gat_W (32 rows) + fused el/er ----
        const int r0 = bid * 32;
        for (int i = tid; i < 32 * 32; i += 128) {
            int rr = i >> 5, c4 = i & 31;
            int row = r0 + rr;
            float4 v = make_float4(0.f, 0.f, 0.f, 0.f);
            if (row < NNODE)
                v = (row < DXV) ? ((const float4*)dxEmb)[row * 32 + c4]
                                : ((const float4*)extra)[(row - DXV) * 32 + c4];
            sn4[i] = v;
        }
        __syncthreads();
        float2 al2 = __ldg((const float2*)(al + c0));
        float2 ar2 = __ldg((const float2*)(ar + c0));
        const ulonglong2* sn = (const ulonglong2*)sn4 + rowgrp * 16 * 32;
        gemm16x2<32>(sn, W + c0, Dm,
            [&](int rr, float v0, float v1) {
                int row = r0 + rowgrp * 16 + rr;
                if (row < NNODE) {
                    g_h[(long)row * Dm + c0]     = v0;
                    g_h[(long)row * Dm + c0 + 1] = v1;
                }
                float p = warpSum(v0 * al2.x + v1 * al2.y);
                float q = warpSum(v0 * ar2.x + v1 * ar2.y);
                if (lane == 0) {
                    pel[rowgrp * 16 + rr][wp2] = p;
                    per[rowgrp * 16 + rr][wp2] = q;
                }
            });
        __syncthreads();
        if (tid < 32) {
            int row = r0 + tid;
            if (row < NNODE) g_el[row] = pel[tid][0] + pel[tid][1];
        } else if (tid < 64) {
            int rr = tid - 32, row = r0 + rr;
            if (row < NNODE) g_er[row] = per[rr][0] + per[rr][1];
        }
    } else if (bid < B_H + B_DR) {
        // ---- drug score (K=256): drEmb@W[0:128] + drEmb2@W[128:256] ----
        const int r0 = (bid - B_H) * 32;
        for (int i = tid; i < 32 * 64; i += 128) {
            int rr = i >> 6, c4 = i & 63;
            int row = r0 + rr;
            float4 v = make_float4(0.f, 0.f, 0.f, 0.f);
            if (row < DRV)
                v = (c4 < 32) ? ((const float4*)drEmb)[row * 32 + c4]
                              : ((const float4*)drEmb2)[row * 32 + (c4 - 32)];
            sn4[i] = v;
        }
        __syncthreads();
        const ulonglong2* sn = (const ulonglong2*)sn4 + rowgrp * 16 * 64;
        gemm16x2<64>(sn, attnW + c0, Dm,
            [&](int rr, float v0, float v1) {
                int row = r0 + rowgrp * 16 + rr;
                if (row < DRV) {
                    g_Sdrug[(long)row * Dm + c0]     = v0;
                    g_Sdrug[(long)row * Dm + c0 + 1] = v1;
                }
            });
    } else if (bid < B_H + B_DR + B_SDX) {
        // ---- Sdx static half (K=128): dxEmb @ attnW[0:128] ----
        const int r0 = (bid - B_H - B_DR) * 32;
        for (int i = tid; i < 32 * 32; i += 128) {
            int rr = i >> 5, c4 = i & 31;
            int row = r0 + rr;
            sn4[i] = (row < DXV) ? ((const float4*)dxEmb)[row * 32 + c4]
                                 : make_float4(0.f, 0.f, 0.f, 0.f);
        }
        __syncthreads();
        const ulonglong2* sn = (const ulonglong2*)sn4 + rowgrp * 16 * 32;
        gemm16x2<32>(sn, attnW + c0, Dm,
            [&](int rr, float v0, float v1) {
                int row = r0 + rowgrp * 16 + rr;
                if (row < DXV) {
                    g_SdxA[(long)row * Dm + c0]     = v0;
                    g_SdxA[(long)row * Dm + c0 + 1] = v1;
                }
            });
    } else {
        // ---- edge count (g_count zeroed at load / by k_scatter) ----
        int cb = bid - B_H - B_DR - B_SDX;
        #pragma unroll
        for (int q = 0; q < 4; q++) {
            int i = cb * 512 + q * 128 + tid;
            if (i < ECNT) {
                int d = edst[i];
                if (d < DXV) g_rank[i] = atomicAdd(&g_count[d], 1);
            }
        }
    }
}

// =====================================================================
// L2: single-block two-level exclusive scan (1024 thr, 10 elems each)
// =====================================================================
__global__ void k_scan() {
    __shared__ int wsum[32];
    const int tid = threadIdx.x, l = tid & 31, w = tid >> 5;
    int pre[10];
    int s = 0;
    #pragma unroll
    for (int k = 0; k < 10; k++) {
        int idx = tid * 10 + k;
        int v = (idx < DXV) ? g_count[idx] : 0;
        pre[k] = s; s += v;
    }
    int x = s;
    #pragma unroll
    for (int o = 1; o < 32; o <<= 1) {
        int y = __shfl_up_sync(0xffffffffu, x, o);
        if (l >= o) x += y;
    }
    if (l == 31) wsum[w] = x;
    __syncthreads();
    if (w == 0) {
        int ws = wsum[l];
        #pragma unroll
        for (int o = 1; o < 32; o <<= 1) {
            int y = __shfl_up_sync(0xffffffffu, ws, o);
            if (l >= o) ws += y;
        }
        wsum[l] = ws;
    }
    __syncthreads();
    int texcl = ((w > 0) ? wsum[w - 1] : 0) + x - s;
    #pragma unroll
    for (int k = 0; k < 10; k++) {
        int idx = tid * 10 + k;
        if (idx < DXV) g_rowoff[idx] = texcl + pre[k];
    }
    if (tid == 0) g_rowoff[DXV] = wsum[31];
}

// =====================================================================
// L3: atomic-free scatter + re-zero counts for next call
// =====================================================================
__global__ void k_scatter(const int* __restrict__ dst) {
    int i = blockIdx.x * blockDim.x + threadIdx.x;
    if (i < ECNT) {
        int d = dst[i];
        if (d < DXV) g_eid[g_rowoff[d] + g_rank[i]] = i;
    }
    if (i < DXV) g_count[i] = 0;
}

// =====================================================================
// L4 (profiled slot): classEmb = L2norm(sparse(dx2anc row) @ S)
// =====================================================================
__global__ void k_classEmb(const float* __restrict__ A, const float* __restrict__ S) {
    const int row = blockIdx.x, tid = threadIdx.x;
    const int l = tid & 31, w = tid >> 5;
    __shared__ float sval[512];
    __shared__ short sidx[512];
    __shared__ int   scnt[4];
    __shared__ float sred[4];
    const float4* r4 = (const float4*)(A + (long)row * NANC);

    float4 va[4];
    #pragma unroll
    for (int q = 0; q < 4; q++) {
        int f4 = tid * 4 + q;
        va[q] = (f4 < NANC / 4) ? __ldg(r4 + f4) : make_float4(0.f, 0.f, 0.f, 0.f);
    }
    const float* vf = (const float*)va;
    int base = 0;
    #pragma unroll
    for (int t = 0; t < 16; t++) {
        float v = vf[t];
        int a = tid * 16 + t;
        bool nz = (v != 0.f);
        unsigned mask = __ballot_sync(0xffffffffu, nz);
        if (nz) {
            int p = base + __popc(mask & ((1u << l) - 1u));
            if (p < 128) { sval[w * 128 + p] = v; sidx[w * 128 + p] = (short)a; }
        }
        base += __popc(mask);
    }
    if (l == 0) scnt[w] = (base < 128) ? base : 128;
    __syncthreads();
    float acc = 0.f;
    for (int ww = 0; ww < 4; ww++) {
        int c = scnt[ww];
        #pragma unroll 2
        for (int j = 0; j < c; j++)
            acc += sval[ww * 128 + j] * __ldg(S + (int)sidx[ww * 128 + j] * Dm + tid);
    }
    float ss = blockSum128(acc * acc, sred);
    g_classEmb[(long)row * Dm + tid] = acc / (sqrtf(ss) + 1e-12f);
}

// =====================================================================
// L5: GAT softmax-aggregate per dst + fuse classEmb (warp-split j)
// =====================================================================
__global__ void k_agg(const int* __restrict__ esrc) {
    const int d = blockIdx.x, tid = threadIdx.x;
    const int lane = tid & 31, w = tid >> 5;
    __shared__ int   sid[MAXDEG];
    __shared__ int   ssrc[MAXDEG];
    __shared__ float sw[MAXDEG];
    __shared__ float shred[4];
    __shared__ float spart[4][128];

    int base = g_rowoff[d];
    int n = g_rowoff[d + 1] - base;
    if (n > MAXDEG) n = MAXDEG;

    for (int j = tid; j < n; j += 128) sid[j] = g_eid[base + j];
    __syncthreads();
    // deterministic ascending edge-id order via rank sort (ids unique, n small)
    for (int j = tid; j < n; j += 128) {
        int id = sid[j];
        int rk = 0;
        for (int k = 0; k < n; k++) rk += (sid[k] < id);
        ssrc[rk] = id;
    }
    __syncthreads();
    float er_d = g_er[d];
    for (int j = tid; j < n; j += 128) {
        int s = esrc[ssrc[j]];
        float x = g_el[s] + er_d;
        sw[j] = (x >= 0.f) ? x : 0.2f * x;
        ssrc[j] = s;
    }
    __syncthreads();
    float m = -1e30f;
    for (int j = tid; j < n; j += 128) m = fmaxf(m, sw[j]);
    m = blockMax128(m, shred);
    float ps = 0.f;
    for (int j = tid; j < n; j += 128) {
        float ww = __expf(sw[j] - m);
        sw[j] = ww;
        ps += ww;
    }
    float inv = 1.f / (blockSum128(ps, shred) + 1e-9f);

    // warp-split aggregate: warp w takes j ≡ w (mod 4); fixed order => deterministic
    float a0 = 0.f, a1 = 0.f, a2 = 0.f, a3 = 0.f;
    #pragma unroll 2
    for (int j = w; j < n; j += 4) {
        float wt = sw[j];
        const float* hp = g_h + (long)ssrc[j] * Dm + lane;
        a0 += wt * hp[0];
        a1 += wt * hp[32];
        a2 += wt * hp[64];
        a3 += wt * hp[96];
    }
    spart[w][lane]      = a0;
    spart[w][lane + 32] = a1;
    spart[w][lane + 64] = a2;
    spart[w][lane + 96] = a3;
    __syncthreads();
    float acc = spart[0][tid] + spart[1][tid] + spart[2][tid] + spart[3][tid];
    g_dxALLonto[(long)d * Dm + tid] = acc * inv + g_classEmb[(long)d * Dm + tid];
}

// =====================================================================
// L6: Sdx = SdxA + dxALLonto @ attnW[128:256]   (K=128 only)
// =====================================================================
__global__ void k_scoreDx2(const float* __restrict__ attnW) {
    __shared__ __align__(16) float4 sn4[32 * 32];   // 16KB
    const int tid = threadIdx.x;
    const int t64 = tid & 63, rowgrp = tid >> 6;
    const int c0 = 2 * t64;
    const int r0 = blockIdx.x * 32;
    for (int i = tid; i < 32 * 32; i += 128) {
        int rr = i >> 5, c4 = i & 31;
        int row = r0 + rr;
        sn4[i] = (row < DXV) ? ((const float4*)g_dxALLonto)[row * 32 + c4]
                             : make_float4(0.f, 0.f, 0.f, 0.f);
    }
    __syncthreads();
    const ulonglong2* sn = (const ulonglong2*)sn4 + rowgrp * 16 * 32;
    gemm16x2<32>(sn, attnW + Dm * Dm + c0, Dm,
        [&](int rr, float v0, float v1) {
            int row = r0 + rowgrp * 16 + rr;
            if (row < DXV) {
                float2 sa = __ldg((const float2*)(g_SdxA + (long)row * Dm + c0));
                g_Sdx[(long)row * Dm + c0]     = v0 + sa.x;
                g_Sdx[(long)row * Dm + c0 + 1] = v1 + sa.y;
            }
        });
}

// =====================================================================
// L7: per-visit attention
// =====================================================================
__global__ void k_visit(const int* __restrict__ dxseqs, const int* __restrict__ drugseqs,
                        const float* __restrict__ dxEmb, const float* __restrict__ drEmb,
                        const float* __restrict__ drEmb2, const float* __restrict__ attnW,
                        const float* __restrict__ attnB, const float* __restrict__ combW,
                        const float* __restrict__ combB) {
    const int bv = blockIdx.x, tid = threadIdx.x;
    __shared__ int   sh_idx[NCODE];
    __shared__ __align__(16) float s_u[256];
    __shared__ float s_up[Dm];
    __shared__ float s_sc[NCODE];
    __shared__ float s_alpha[NCODE];
    __shared__ float shred[4];

    if (tid < NDX)        sh_idx[tid] = dxseqs[bv * NDX + tid];
    else if (tid < NCODE) sh_idx[tid] = drugseqs[bv * NDX + (tid - NDX)];
    __syncthreads();

    float u0 = 0.f, u1 = 0.f;
    #pragma unroll 4
    for (int k = 0; k < NCODE; k++) {
        int id = sh_idx[k];
        const float *p0, *p1;
        if (k < NDX) { p0 = dxEmb + (long)id * Dm; p1 = g_dxALLonto + (long)id * Dm; }
        else         { p0 = drEmb + (long)id * Dm; p1 = drEmb2 + (long)id * Dm; }
        u0 += p0[tid];
        u1 += p1[tid];
    }
    s_u[tid] = u0 * (1.f / NCODE);
    s_u[Dm + tid] = u1 * (1.f / NCODE);
    __syncthreads();

    {   // u_part = u @ attnW[256:512] + attn_b   (k-paired FFMA2)
        const ULL* su64 = (const ULL*)s_u;
        ULL up2 = 0ull;
        #pragma unroll 4
        for (int k2 = 0; k2 < 128; k2++) {
            ULL wv = pk2(__ldg(attnW + (256 + 2 * k2) * Dm + tid),
                         __ldg(attnW + (257 + 2 * k2) * Dm + tid));
            ffma2(up2, su64[k2], wv);
        }
        s_up[tid] = __ldg(attnB + tid) + fold2(up2);
    }
    __syncthreads();

    const int w = tid >> 5, lane = tid & 31;
    const float cb = __ldg(combB);
    for (int k = w; k < NCODE; k += 4) {
        int id = sh_idx[k];
        const float* base = (k < NDX) ? (g_Sdx + (long)id * Dm) : (g_Sdrug + (long)id * Dm);
        float t = 0.f;
        #pragma unroll
        for (int q = 0; q < 4; q++) {
            int d = lane + 32 * q;
            t += fast_tanh(base[d] + s_up[d]) * __ldg(combW + d);
        }
        t = warpSum(t);
        if (lane == 0) s_sc[k] = t + cb;
    }
    __syncthreads();

    float sv = (tid < NCODE) ? s_sc[tid] : -1e30f;
    float m = blockMax128(sv, shred);
    float e = (tid < NCODE) ? __expf(sv - m) : 0.f;
    float Z = blockSum128(e, shred);
    if (tid < NCODE) s_alpha[tid] = e / Z;
    __syncthreads();

    float v0 = 0.f, v1 = 0.f;
    #pragma unroll 4
    for (int k = 0; k < NCODE; k++) {
        float a = s_alpha[k];
        int id = sh_idx[k];
        const float *p0, *p1;
        if (k < NDX) { p0 = dxEmb + (long)id * Dm; p1 = g_dxALLonto + (long)id * Dm; }
        else         { p0 = drEmb + (long)id * Dm; p1 = drEmb2 + (long)id * Dm; }
        v0 += a * p0[tid];
        v1 += a * p1[tid];
    }
    g_visit[bv * 256 + tid] = v0;
    g_visit[bv * 256 + Dm + tid] = v1;
}

// =====================================================================
// L8: out = sigmoid(visit @ dp_W + dp_b)   (32 rows x 128 cols per block)
// =====================================================================
__global__ void k_dp(const float* __restrict__ dpW, const float* __restrict__ dpB,
                     float* __restrict__ out) {
    __shared__ __align__(16) float4 sv4[32 * 64];   // 32KB
    const int tid = threadIdx.x;
    const int t64 = tid & 63, rowgrp = tid >> 6;
    const int c0 = blockIdx.x * 128 + 2 * t64;
    const int r0 = blockIdx.y * 32;
    for (int i = tid; i < 32 * 64; i += 128)
        sv4[i] = ((const float4*)g_visit)[r0 * 64 + i];
    __syncthreads();
    if (c0 >= LBL) return;   // LBL even -> pairs never straddle
    float2 b2 = __ldg((const float2*)(dpB + c0));
    const ulonglong2* sn = (const ulonglong2*)sv4 + rowgrp * 16 * 64;
    gemm16x2<64>(sn, dpW + c0, LBL,
        [&](int rr, float v0, float v1) {
            int row = r0 + rowgrp * 16 + rr;
            out[(long)row * LBL + c0]     = 1.f / (1.f + __expf(-(v0 + b2.x)));
            out[(long)row * LBL + c0 + 1] = 1.f / (1.f + __expf(-(v1 + b2.y)));
        });
}

// ---------------- launcher ----------------
extern "C" void kernel_launch(void* const* d_in, const int* in_sizes, int n_in,
                              void* d_out, int out_size) {
    const int*   dxseqs  = (const int*)d_in[0];
    const int*   drugseqs= (const int*)d_in[1];
    const int*   esrc    = (const int*)d_in[2];
    const int*   edst    = (const int*)d_in[3];
    const float* dx2anc  = (const float*)d_in[4];
    const float* dxEmb   = (const float*)d_in[5];
    const float* drEmb   = (const float*)d_in[6];
    const float* drEmb2  = (const float*)d_in[7];
    const float* extra   = (const float*)d_in[8];
    const float* S       = (const float*)d_in[9];
    const float* gatW    = (const float*)d_in[10];
    const float* gal     = (const float*)d_in[11];
    const float* gar     = (const float*)d_in[12];
    const float* attnW   = (const float*)d_in[13];
    const float* attnB   = (const float*)d_in[14];
    const float* combW   = (const float*)d_in[15];
    const float* combB   = (const float*)d_in[16];
    const float* dpW     = (const float*)d_in[17];
    const float* dpB     = (const float*)d_in[18];
    float*       out     = (float*)d_out;

    // k_classEmb lands in the profiler's captured slot (4th launch).
    k_front<<<B_H + B_DR + B_SDX + B_CNT, 128>>>(dxEmb, extra, gatW, gal, gar,
                                                 drEmb, drEmb2, attnW, edst);
    k_scan<<<1, 1024>>>();
    k_scatter<<<(ECNT + 255) / 256, 256>>>(edst);
    k_classEmb<<<DXV, 128>>>(dx2anc, S);
    k_agg<<<DXV, 128>>>(esrc);
    k_scoreDx2<<<B_SDX, 128>>>(attnW);
    k_visit<<<NBV, 128>>>(dxseqs, drugseqs, dxEmb, drEmb, drEmb2,
                          attnW, attnB, combW, combB);
    k_dp<<<dim3((LBL + 127) / 128, NBV / 32), 128>>>(dpW, dpB, out);
}

// round 11
// speedup vs baseline: 1.0667x; 1.0059x over previous
#include <cuda_runtime.h>
#include <math.h>

// ---------------- problem constants ----------------
#define DXV   10000
#define DRV   5000
#define NANC  2000
#define NNODE 18000     // DXV + SPLIT*NANC
#define Dm    128
#define ECNT  200000
#define NBV   640       // B*V
#define NCODE 80
#define NDX   40
#define LBL   2000
#define MAXDEG 192

#define B_H    563      // ceil(18000/32)
#define B_DR   157      // ceil(5000/32)
#define B_SDX  313      // ceil(10000/32)
#define B_CNT  391      // ceil(200000/512)

typedef unsigned long long ULL;

// ---------------- scratch ----------------
__device__ float g_h[NNODE * Dm];
__device__ float g_el[NNODE];
__device__ float g_er[NNODE];
__device__ int   g_count[DXV];      // zero at load; re-zeroed by k_scatter each call
__device__ int   g_rowoff[DXV + 1];
__device__ int   g_rank[ECNT];
__device__ int   g_eid[ECNT];
__device__ float g_dxALLonto[DXV * Dm];
__device__ float g_SdxA[DXV * Dm];  // static half: dxEmb @ attnW[0:128]
__device__ float g_Sdx[DXV * Dm];
__device__ float g_Sdrug[DRV * Dm];
__device__ float g_visit[NBV * 2 * Dm];

// ---------------- helpers ----------------
__device__ __forceinline__ float warpSum(float x) {
    #pragma unroll
    for (int o = 16; o; o >>= 1) x += __shfl_xor_sync(0xffffffffu, x, o);
    return x;
}
__device__ __forceinline__ float warpMax(float x) {
    #pragma unroll
    for (int o = 16; o; o >>= 1) x = fmaxf(x, __shfl_xor_sync(0xffffffffu, x, o));
    return x;
}
__device__ __forceinline__ float blockSum128(float x, float* sh) {
    int w = threadIdx.x >> 5, l = threadIdx.x & 31;
    x = warpSum(x);
    if (l == 0) sh[w] = x;
    __syncthreads();
    float r = sh[0] + sh[1] + sh[2] + sh[3];
    __syncthreads();
    return r;
}
__device__ __forceinline__ float blockMax128(float x, float* sh) {
    int w = threadIdx.x >> 5, l = threadIdx.x & 31;
    x = warpMax(x);
    if (l == 0) sh[w] = x;
    __syncthreads();
    float r = fmaxf(fmaxf(sh[0], sh[1]), fmaxf(sh[2], sh[3]));
    __syncthreads();
    return r;
}
__device__ __forceinline__ float fast_tanh(float x) {
    float y;
    asm("tanh.approx.f32 %0, %1;" : "=f"(y) : "f"(x));
    return y;
}
// packed fp32x2 FMA (FFMA2)
__device__ __forceinline__ ULL pk2(float lo, float hi) {
    ULL r; asm("mov.b64 %0, {%1, %2};" : "=l"(r) : "f"(lo), "f"(hi)); return r;
}
__device__ __forceinline__ void ffma2(ULL& d, ULL a, ULL b) {
    asm("fma.rn.f32x2 %0, %1, %2, %0;" : "+l"(d) : "l"(a), "l"(b));
}
__device__ __forceinline__ float fold2(ULL a) {
    float lo, hi; asm("mov.b64 {%0, %1}, %2;" : "=f"(lo), "=f"(hi) : "l"(a));
    return lo + hi;
}

// 16-row x 2-col GEMM tile core (k-paired FFMA2), K = 4*K4.
template<int K4, class F>
__device__ __forceinline__ void gemm16x2(const ulonglong2* __restrict__ sn,
                                         const float* __restrict__ wbase, int wstride,
                                         F emit) {
    ULL acc0[16], acc1[16];
    #pragma unroll
    for (int r = 0; r < 16; r++) { acc0[r] = 0ull; acc1[r] = 0ull; }
    #pragma unroll 2
    for (int k4 = 0; k4 < K4; k4++) {
        const float* wp = wbase + (k4 * 4) * wstride;
        float2 v0 = __ldg((const float2*)(wp));
        float2 v1 = __ldg((const float2*)(wp + wstride));
        float2 v2 = __ldg((const float2*)(wp + 2 * wstride));
        float2 v3 = __ldg((const float2*)(wp + 3 * wstride));
        ULL w01a = pk2(v0.x, v1.x), w01b = pk2(v0.y, v1.y);
        ULL w23a = pk2(v2.x, v3.x), w23b = pk2(v2.y, v3.y);
        #pragma unroll
        for (int r = 0; r < 16; r++) {
            ulonglong2 x = sn[r * K4 + k4];
            ffma2(acc0[r], x.x, w01a);
            ffma2(acc0[r], x.y, w23a);
            ffma2(acc1[r], x.x, w01b);
            ffma2(acc1[r], x.y, w23b);
        }
    }
    #pragma unroll
    for (int r = 0; r < 16; r++) emit(r, fold2(acc0[r]), fold2(acc1[r]));
}

// =====================================================================
// L1 FRONT: h+el/er | drug score | Sdx static | edge count
// =====================================================================
__global__ void k_front(const float* __restrict__ dxEmb, const float* __restrict__ extra,
                        const float* __restrict__ W, const float* __restrict__ al,
                        const float* __restrict__ ar,
                        const float* __restrict__ drEmb, const float* __restrict__ drEmb2,
                        const float* __restrict__ attnW,
                        const int* __restrict__ edst) {
    __shared__ __align__(16) float4 sn4[32 * 64];   // 32KB
    __shared__ float pel[32][2];
    __shared__ float per[32][2];
    const int bid = blockIdx.x, tid = threadIdx.x;
    const int lane = tid & 31, wp2 = (tid >> 5) & 1;
    const int t64 = tid & 63, rowgrp = tid >> 6;
    const int c0 = 2 * t64;

    if (bid < B_H) {
        // ---- h = nodes @ gat_W (32 rows) + fused el/er ----
        const int r0 = bid * 32;
        for (int i = tid; i < 32 * 32; i += 128) {
            int rr = i >> 5, c4 = i & 31;
            int row = r0 + rr;
            float4 v = make_float4(0.f, 0.f, 0.f, 0.f);
            if (row < NNODE)
                v = (row < DXV) ? ((const float4*)dxEmb)[row * 32 + c4]
                                : ((const float4*)extra)[(row - DXV) * 32 + c4];
            sn4[i] = v;
        }
        __syncthreads();
        float2 al2 = __ldg((const float2*)(al + c0));
        float2 ar2 = __ldg((const float2*)(ar + c0));
        const ulonglong2* sn = (const ulonglong2*)sn4 + rowgrp * 16 * 32;
        gemm16x2<32>(sn, W + c0, Dm,
            [&](int rr, float v0, float v1) {
                int row = r0 + rowgrp * 16 + rr;
                if (row < NNODE) {
                    g_h[(long)row * Dm + c0]     = v0;
                    g_h[(long)row * Dm + c0 + 1] = v1;
                }
                float p = warpSum(v0 * al2.x + v1 * al2.y);
                float q = warpSum(v0 * ar2.x + v1 * ar2.y);
                if (lane == 0) {
                    pel[rowgrp * 16 + rr][wp2] = p;
                    per[rowgrp * 16 + rr][wp2] = q;
                }
            });
        __syncthreads();
        if (tid < 32) {
            int row = r0 + tid;
            if (row < NNODE) g_el[row] = pel[tid][0] + pel[tid][1];
        } else if (tid < 64) {
            int rr = tid - 32, row = r0 + rr;
            if (row < NNODE) g_er[row] = per[rr][0] + per[rr][1];
        }
    } else if (bid < B_H + B_DR) {
        // ---- drug score (K=256): drEmb@W[0:128] + drEmb2@W[128:256] ----
        const int r0 = (bid - B_H) * 32;
        for (int i = tid; i < 32 * 64; i += 128) {
            int rr = i >> 6, c4 = i & 63;
            int row = r0 + rr;
            float4 v = make_float4(0.f, 0.f, 0.f, 0.f);
            if (row < DRV)
                v = (c4 < 32) ? ((const float4*)drEmb)[row * 32 + c4]
                              : ((const float4*)drEmb2)[row * 32 + (c4 - 32)];
            sn4[i] = v;
        }
        __syncthreads();
        const ulonglong2* sn = (const ulonglong2*)sn4 + rowgrp * 16 * 64;
        gemm16x2<64>(sn, attnW + c0, Dm,
            [&](int rr, float v0, float v1) {
                int row = r0 + rowgrp * 16 + rr;
                if (row < DRV) {
                    g_Sdrug[(long)row * Dm + c0]     = v0;
                    g_Sdrug[(long)row * Dm + c0 + 1] = v1;
                }
            });
    } else if (bid < B_H + B_DR + B_SDX) {
        // ---- Sdx static half (K=128): dxEmb @ attnW[0:128] ----
        const int r0 = (bid - B_H - B_DR) * 32;
        for (int i = tid; i < 32 * 32; i += 128) {
            int rr = i >> 5, c4 = i & 31;
            int row = r0 + rr;
            sn4[i] = (row < DXV) ? ((const float4*)dxEmb)[row * 32 + c4]
                                 : make_float4(0.f, 0.f, 0.f, 0.f);
        }
        __syncthreads();
        const ulonglong2* sn = (const ulonglong2*)sn4 + rowgrp * 16 * 32;
        gemm16x2<32>(sn, attnW + c0, Dm,
            [&](int rr, float v0, float v1) {
                int row = r0 + rowgrp * 16 + rr;
                if (row < DXV) {
                    g_SdxA[(long)row * Dm + c0]     = v0;
                    g_SdxA[(long)row * Dm + c0 + 1] = v1;
                }
            });
    } else {
        // ---- edge count ----
        int cb = bid - B_H - B_DR - B_SDX;
        #pragma unroll
        for (int q = 0; q < 4; q++) {
            int i = cb * 512 + q * 128 + tid;
            if (i < ECNT) {
                int d = edst[i];
                if (d < DXV) g_rank[i] = atomicAdd(&g_count[d], 1);
            }
        }
    }
}

// =====================================================================
// L2: single-block two-level exclusive scan (1024 thr, 10 elems each)
// =====================================================================
__global__ void k_scan() {
    __shared__ int wsum[32];
    const int tid = threadIdx.x, l = tid & 31, w = tid >> 5;
    int pre[10];
    int s = 0;
    #pragma unroll
    for (int k = 0; k < 10; k++) {
        int idx = tid * 10 + k;
        int v = (idx < DXV) ? g_count[idx] : 0;
        pre[k] = s; s += v;
    }
    int x = s;
    #pragma unroll
    for (int o = 1; o < 32; o <<= 1) {
        int y = __shfl_up_sync(0xffffffffu, x, o);
        if (l >= o) x += y;
    }
    if (l == 31) wsum[w] = x;
    __syncthreads();
    if (w == 0) {
        int ws = wsum[l];
        #pragma unroll
        for (int o = 1; o < 32; o <<= 1) {
            int y = __shfl_up_sync(0xffffffffu, ws, o);
            if (l >= o) ws += y;
        }
        wsum[l] = ws;
    }
    __syncthreads();
    int texcl = ((w > 0) ? wsum[w - 1] : 0) + x - s;
    #pragma unroll
    for (int k = 0; k < 10; k++) {
        int idx = tid * 10 + k;
        if (idx < DXV) g_rowoff[idx] = texcl + pre[k];
    }
    if (tid == 0) g_rowoff[DXV] = wsum[31];
}

// =====================================================================
// L3: atomic-free scatter + re-zero counts for next call
// =====================================================================
__global__ void k_scatter(const int* __restrict__ dst) {
    int i = blockIdx.x * blockDim.x + threadIdx.x;
    if (i < ECNT) {
        int d = dst[i];
        if (d < DXV) g_eid[g_rowoff[d] + g_rank[i]] = i;
    }
    if (i < DXV) g_count[i] = 0;
}

// =====================================================================
// L4 (profiled slot): FUSED GAT-aggregate + classEmb per dx row
//   dxALLonto[d] = softmax-agg(h over in-edges of d) + L2norm(A[d] @ S)
// =====================================================================
__global__ void k_aggCE(const int* __restrict__ esrc,
                        const float* __restrict__ A, const float* __restrict__ S) {
    const int d = blockIdx.x, tid = threadIdx.x;
    const int lane = tid & 31, w = tid >> 5;
    __shared__ int   sid[MAXDEG];
    __shared__ int   ssrc[MAXDEG];
    __shared__ float sw[MAXDEG];
    __shared__ float shred[4];
    __shared__ float spart[4][128];
    __shared__ float sval[512];
    __shared__ short sidx[512];
    __shared__ int   scnt[4];

    // --- issue the A-row loads first (fly under the CSR phase) ---
    const float4* r4 = (const float4*)(A + (long)d * NANC);
    float4 va[4];
    #pragma unroll
    for (int q = 0; q < 4; q++) {
        int f4 = tid * 4 + q;
        va[q] = (f4 < NANC / 4) ? __ldg(r4 + f4) : make_float4(0.f, 0.f, 0.f, 0.f);
    }

    // --- GAT: CSR load + deterministic sort + edge softmax weights ---
    int base = g_rowoff[d];
    int n = g_rowoff[d + 1] - base;
    if (n > MAXDEG) n = MAXDEG;

    for (int j = tid; j < n; j += 128) sid[j] = g_eid[base + j];
    __syncthreads();
    for (int j = tid; j < n; j += 128) {   // rank sort (ids unique, n small)
        int id = sid[j];
        int rk = 0;
        for (int k = 0; k < n; k++) rk += (sid[k] < id);
        ssrc[rk] = id;
    }
    __syncthreads();
    float er_d = g_er[d];
    for (int j = tid; j < n; j += 128) {
        int s = esrc[ssrc[j]];
        float x = g_el[s] + er_d;
        sw[j] = (x >= 0.f) ? x : 0.2f * x;
        ssrc[j] = s;
    }
    __syncthreads();
    float m = -1e30f;
    for (int j = tid; j < n; j += 128) m = fmaxf(m, sw[j]);
    m = blockMax128(m, shred);
    float ps = 0.f;
    for (int j = tid; j < n; j += 128) {
        float ww = __expf(sw[j] - m);
        sw[j] = ww;
        ps += ww;
    }
    float inv = 1.f / (blockSum128(ps, shred) + 1e-9f);

    // --- classEmb: ballot compaction of the sparse A row ---
    const float* vf = (const float*)va;
    int cbase = 0;
    #pragma unroll
    for (int t = 0; t < 16; t++) {
        float v = vf[t];
        int a = tid * 16 + t;
        bool nz = (v != 0.f);
        unsigned mask = __ballot_sync(0xffffffffu, nz);
        if (nz) {
            int p = cbase + __popc(mask & ((1u << lane) - 1u));
            if (p < 128) { sval[w * 128 + p] = v; sidx[w * 128 + p] = (short)a; }
        }
        cbase += __popc(mask);
    }
    if (lane == 0) scnt[w] = (cbase < 128) ? cbase : 128;
    __syncthreads();

    // --- interleavable gathers: S rows (classEmb) and h rows (GAT) ---
    float ce = 0.f;
    for (int ww = 0; ww < 4; ww++) {
        int c = scnt[ww];
        #pragma unroll 2
        for (int j = 0; j < c; j++)
            ce += sval[ww * 128 + j] * __ldg(S + (int)sidx[ww * 128 + j] * Dm + tid);
    }

    // warp-split aggregate: warp w takes j ≡ w (mod 4); fixed order => deterministic
    float a0 = 0.f, a1 = 0.f, a2 = 0.f, a3 = 0.f;
    #pragma unroll 2
    for (int j = w; j < n; j += 4) {
        float wt = sw[j];
        const float* hp = g_h + (long)ssrc[j] * Dm + lane;
        a0 += wt * hp[0];
        a1 += wt * hp[32];
        a2 += wt * hp[64];
        a3 += wt * hp[96];
    }
    spart[w][lane]      = a0;
    spart[w][lane + 32] = a1;
    spart[w][lane + 64] = a2;
    spart[w][lane + 96] = a3;

    // classEmb L2 norm (blockSum has its own syncs; also covers spart)
    float ss = blockSum128(ce * ce, shred);
    float cen = ce / (sqrtf(ss) + 1e-12f);

    float acc = spart[0][tid] + spart[1][tid] + spart[2][tid] + spart[3][tid];
    g_dxALLonto[(long)d * Dm + tid] = acc * inv + cen;
}

// =====================================================================
// L5: Sdx = SdxA + dxALLonto @ attnW[128:256]   (K=128 only)
// =====================================================================
__global__ void k_scoreDx2(const float* __restrict__ attnW) {
    __shared__ __align__(16) float4 sn4[32 * 32];   // 16KB
    const int tid = threadIdx.x;
    const int t64 = tid & 63, rowgrp = tid >> 6;
    const int c0 = 2 * t64;
    const int r0 = blockIdx.x * 32;
    for (int i = tid; i < 32 * 32; i += 128) {
        int rr = i >> 5, c4 = i & 31;
        int row = r0 + rr;
        sn4[i] = (row < DXV) ? ((const float4*)g_dxALLonto)[row * 32 + c4]
                             : make_float4(0.f, 0.f, 0.f, 0.f);
    }
    __syncthreads();
    const ulonglong2* sn = (const ulonglong2*)sn4 + rowgrp * 16 * 32;
    gemm16x2<32>(sn, attnW + Dm * Dm + c0, Dm,
        [&](int rr, float v0, float v1) {
            int row = r0 + rowgrp * 16 + rr;
            if (row < DXV) {
                float2 sa = __ldg((const float2*)(g_SdxA + (long)row * Dm + c0));
                g_Sdx[(long)row * Dm + c0]     = v0 + sa.x;
                g_Sdx[(long)row * Dm + c0 + 1] = v1 + sa.y;
            }
        });
}

// =====================================================================
// L6: per-visit attention
// =====================================================================
__global__ void k_visit(const int* __restrict__ dxseqs, const int* __restrict__ drugseqs,
                        const float* __restrict__ dxEmb, const float* __restrict__ drEmb,
                        const float* __restrict__ drEmb2, const float* __restrict__ attnW,
                        const float* __restrict__ attnB, const float* __restrict__ combW,
                        const float* __restrict__ combB) {
    const int bv = blockIdx.x, tid = threadIdx.x;
    __shared__ int   sh_idx[NCODE];
    __shared__ __align__(16) float s_u[256];
    __shared__ float s_up[Dm];
    __shared__ float s_sc[NCODE];
    __shared__ float s_alpha[NCODE];
    __shared__ float shred[4];

    if (tid < NDX)        sh_idx[tid] = dxseqs[bv * NDX + tid];
    else if (tid < NCODE) sh_idx[tid] = drugseqs[bv * NDX + (tid - NDX)];
    __syncthreads();

    float u0 = 0.f, u1 = 0.f;
    #pragma unroll 4
    for (int k = 0; k < NCODE; k++) {
        int id = sh_idx[k];
        const float *p0, *p1;
        if (k < NDX) { p0 = dxEmb + (long)id * Dm; p1 = g_dxALLonto + (long)id * Dm; }
        else         { p0 = drEmb + (long)id * Dm; p1 = drEmb2 + (long)id * Dm; }
        u0 += p0[tid];
        u1 += p1[tid];
    }
    s_u[tid] = u0 * (1.f / NCODE);
    s_u[Dm + tid] = u1 * (1.f / NCODE);
    __syncthreads();

    {   // u_part = u @ attnW[256:512] + attn_b   (k-paired FFMA2)
        const ULL* su64 = (const ULL*)s_u;
        ULL up2 = 0ull;
        #pragma unroll 4
        for (int k2 = 0; k2 < 128; k2++) {
            ULL wv = pk2(__ldg(attnW + (256 + 2 * k2) * Dm + tid),
                         __ldg(attnW + (257 + 2 * k2) * Dm + tid));
            ffma2(up2, su64[k2], wv);
        }
        s_up[tid] = __ldg(attnB + tid) + fold2(up2);
    }
    __syncthreads();

    const int w = tid >> 5, lane = tid & 31;
    const float cb = __ldg(combB);
    for (int k = w; k < NCODE; k += 4) {
        int id = sh_idx[k];
        const float* base = (k < NDX) ? (g_Sdx + (long)id * Dm) : (g_Sdrug + (long)id * Dm);
        float t = 0.f;
        #pragma unroll
        for (int q = 0; q < 4; q++) {
            int dcol = lane + 32 * q;
            t += fast_tanh(base[dcol] + s_up[dcol]) * __ldg(combW + dcol);
        }
        t = warpSum(t);
        if (lane == 0) s_sc[k] = t + cb;
    }
    __syncthreads();

    float sv = (tid < NCODE) ? s_sc[tid] : -1e30f;
    float m = blockMax128(sv, shred);
    float e = (tid < NCODE) ? __expf(sv - m) : 0.f;
    float Z = blockSum128(e, shred);
    if (tid < NCODE) s_alpha[tid] = e / Z;
    __syncthreads();

    float v0 = 0.f, v1 = 0.f;
    #pragma unroll 4
    for (int k = 0; k < NCODE; k++) {
        float a = s_alpha[k];
        int id = sh_idx[k];
        const float *p0, *p1;
        if (k < NDX) { p0 = dxEmb + (long)id * Dm; p1 = g_dxALLonto + (long)id * Dm; }
        else         { p0 = drEmb + (long)id * Dm; p1 = drEmb2 + (long)id * Dm; }
        v0 += a * p0[tid];
        v1 += a * p1[tid];
    }
    g_visit[bv * 256 + tid] = v0;
    g_visit[bv * 256 + Dm + tid] = v1;
}

// =====================================================================
// L7: out = sigmoid(visit @ dp_W + dp_b)   (32 rows x 128 cols per block)
// =====================================================================
__global__ void k_dp(const float* __restrict__ dpW, const float* __restrict__ dpB,
                     float* __restrict__ out) {
    __shared__ __align__(16) float4 sv4[32 * 64];   // 32KB
    const int tid = threadIdx.x;
    const int t64 = tid & 63, rowgrp = tid >> 6;
    const int c0 = blockIdx.x * 128 + 2 * t64;
    const int r0 = blockIdx.y * 32;
    for (int i = tid; i < 32 * 64; i += 128)
        sv4[i] = ((const float4*)g_visit)[r0 * 64 + i];
    __syncthreads();
    if (c0 >= LBL) return;   // LBL even -> pairs never straddle
    float2 b2 = __ldg((const float2*)(dpB + c0));
    const ulonglong2* sn = (const ulonglong2*)sv4 + rowgrp * 16 * 64;
    gemm16x2<64>(sn, dpW + c0, LBL,
        [&](int rr, float v0, float v1) {
            int row = r0 + rowgrp * 16 + rr;
            out[(long)row * LBL + c0]     = 1.f / (1.f + __expf(-(v0 + b2.x)));
            out[(long)row * LBL + c0 + 1] = 1.f / (1.f + __expf(-(v1 + b2.y)));
        });
}

// ---------------- launcher ----------------
extern "C" void kernel_launch(void* const* d_in, const int* in_sizes, int n_in,
                              void* d_out, int out_size) {
    const int*   dxseqs  = (const int*)d_in[0];
    const int*   drugseqs= (const int*)d_in[1];
    const int*   esrc    = (const int*)d_in[2];
    const int*   edst    = (const int*)d_in[3];
    const float* dx2anc  = (const float*)d_in[4];
    const float* dxEmb   = (const float*)d_in[5];
    const float* drEmb   = (const float*)d_in[6];
    const float* drEmb2  = (const float*)d_in[7];
    const float* extra   = (const float*)d_in[8];
    const float* S       = (const float*)d_in[9];
    const float* gatW    = (const float*)d_in[10];
    const float* gal     = (const float*)d_in[11];
    const float* gar     = (const float*)d_in[12];
    const float* attnW   = (const float*)d_in[13];
    const float* attnB   = (const float*)d_in[14];
    const float* combW   = (const float*)d_in[15];
    const float* combB   = (const float*)d_in[16];
    const float* dpW     = (const float*)d_in[17];
    const float* dpB     = (const float*)d_in[18];
    float*       out     = (float*)d_out;

    // k_aggCE (fused GAT aggregate + classEmb) lands in profiled slot 4.
    k_front<<<B_H + B_DR + B_SDX + B_CNT, 128>>>(dxEmb, extra, gatW, gal, gar,
                                                 drEmb, drEmb2, attnW, edst);
    k_scan<<<1, 1024>>>();
    k_scatter<<<(ECNT + 255) / 256, 256>>>(edst);
    k_aggCE<<<DXV, 128>>>(esrc, dx2anc, S);
    k_scoreDx2<<<B_SDX, 128>>>(attnW);
    k_visit<<<NBV, 128>>>(dxseqs, drugseqs, dxEmb, drEmb, drEmb2,
                          attnW, attnB, combW, combB);
    k_dp<<<dim3((LBL + 127) / 128, NBV / 32), 128>>>(dpW, dpB, out);
}